// round 4
// baseline (speedup 1.0000x reference)
#include <cuda_runtime.h>
#include <cuda_bf16.h>

// ImagemoveCollisionCost — R3: ILP-2 (two points per thread) to saturate L1tex.
//   state_seq : [8192, 128, 4] f32 (x, y, vx, vy)
//   sdf, grad_y, grad_x : [2048, 2048] f32
// Outputs concatenated: res [N], judge_res [N].

#define W_IMG  2048
#define H_IMG  2048
#define LO    (-1.0f)
#define WV1   (1.0f)
#define WV2   (0.5f)

__device__ __forceinline__ void pick2(float4 q, float e, int off,
                                      float& v0, float& v1)
{
    bool hi = (off & 2) != 0;
    bool lo = (off & 1) != 0;
    v0 = hi ? (lo ? q.w : q.z) : (lo ? q.y : q.x);
    v1 = hi ? (lo ? e   : q.w) : (lo ? q.z : q.y);
}

struct GatherCtx {
    int b0, b1, off;
    bool wrap;
    float fx, fy;
    float vx, vy;
};

__device__ __forceinline__ GatherCtx make_ctx(float4 s)
{
    GatherCtx c;
    const float sc = 0.5f * (float)(W_IMG - 1);
    float px = fminf(fmaxf((s.x - LO) * sc, 0.0f), (float)(W_IMG - 1));
    float py = fminf(fmaxf((s.y - LO) * sc, 0.0f), (float)(H_IMG - 1));
    int x0 = min(max((int)floorf(px), 0), W_IMG - 2);
    int y0 = min(max((int)floorf(py), 0), H_IMG - 2);
    c.fx = px - (float)x0;
    c.fy = py - (float)y0;
    int x0a = x0 & ~3;
    c.off  = x0 - x0a;
    c.b0   = y0 * W_IMG + x0a;
    c.b1   = c.b0 + W_IMG;
    c.wrap = (c.off == 3);
    c.vx = s.z; c.vy = s.w;
    return c;
}

__device__ __forceinline__ void finish(const GatherCtx& c,
                                       float4 S0, float4 S1, float4 A0, float4 A1,
                                       float4 B0, float4 B1,
                                       float se0, float se1, float ae0, float ae1,
                                       float be0, float be1,
                                       float& cost, float& judge)
{
    float s00, s01, s10, s11, a00, a01, a10, a11, c00, c01, c10, c11;
    pick2(S0, se0, c.off, s00, s01);
    pick2(S1, se1, c.off, s10, s11);
    pick2(A0, ae0, c.off, a00, a01);
    pick2(A1, ae1, c.off, a10, a11);
    pick2(B0, be0, c.off, c00, c01);
    pick2(B1, be1, c.off, c10, c11);

    float gx1 = 1.0f - c.fx, gy1 = 1.0f - c.fy;
    float pot = (s00 * gx1 + s01 * c.fx) * gy1 + (s10 * gx1 + s11 * c.fx) * c.fy;
    float gy_ = (a00 * gx1 + a01 * c.fx) * gy1 + (a10 * gx1 + a11 * c.fx) * c.fy;
    float gx_ = (c00 * gx1 + c01 * c.fx) * gy1 + (c10 * gx1 + c11 * c.fx) * c.fy;

    float vel_abs  = sqrtf(c.vx * c.vx + c.vy * c.vy);
    float grad_abs = sqrtf(gx_ * gx_ + gy_ * gy_);
    float dot      = c.vx * gx_ + c.vy * gy_;
    float cosq     = dot / (vel_abs * grad_abs + 1e-6f);
    cosq = fminf(fmaxf(cosq, -1.0f), 1.0f);
    float neg_cos = -cosq;

    float pv     = WV2 * pot * vel_abs;
    judge        = WV1 * pot + pv;
    float factor = 1.0f + fmaxf(neg_cos, 0.0f) + 0.8f * fminf(neg_cos, 0.0f);
    cost         = WV1 * pot + pv * factor;
}

__global__ __launch_bounds__(256, 3)
void imgmove_cost_kernel(const float4* __restrict__ state,
                         const float*  __restrict__ sdf,
                         const float*  __restrict__ gym,
                         const float*  __restrict__ gxm,
                         float*        __restrict__ out_res,
                         float*        __restrict__ out_judge,
                         int n)
{
    int i0 = blockIdx.x * (blockDim.x * 2) + threadIdx.x;
    int i1 = i0 + blockDim.x;
    if (i0 >= n) return;
    bool has2 = (i1 < n);

    float4 sA = state[i0];
    float4 sB = has2 ? state[i1] : sA;

    GatherCtx cA = make_ctx(sA);
    GatherCtx cB = make_ctx(sB);

    // All scattered loads for BOTH points issued back-to-back (max MLP).
    float4 S0a = __ldg((const float4*)(sdf + cA.b0));
    float4 S1a = __ldg((const float4*)(sdf + cA.b1));
    float4 A0a = __ldg((const float4*)(gym + cA.b0));
    float4 A1a = __ldg((const float4*)(gym + cA.b1));
    float4 B0a = __ldg((const float4*)(gxm + cA.b0));
    float4 B1a = __ldg((const float4*)(gxm + cA.b1));
    float4 S0b = __ldg((const float4*)(sdf + cB.b0));
    float4 S1b = __ldg((const float4*)(sdf + cB.b1));
    float4 A0b = __ldg((const float4*)(gym + cB.b0));
    float4 A1b = __ldg((const float4*)(gym + cB.b1));
    float4 B0b = __ldg((const float4*)(gxm + cB.b0));
    float4 B1b = __ldg((const float4*)(gxm + cB.b1));

    float se0a = cA.wrap ? __ldg(sdf + cA.b0 + 4) : 0.0f;
    float se1a = cA.wrap ? __ldg(sdf + cA.b1 + 4) : 0.0f;
    float ae0a = cA.wrap ? __ldg(gym + cA.b0 + 4) : 0.0f;
    float ae1a = cA.wrap ? __ldg(gym + cA.b1 + 4) : 0.0f;
    float be0a = cA.wrap ? __ldg(gxm + cA.b0 + 4) : 0.0f;
    float be1a = cA.wrap ? __ldg(gxm + cA.b1 + 4) : 0.0f;
    float se0b = cB.wrap ? __ldg(sdf + cB.b0 + 4) : 0.0f;
    float se1b = cB.wrap ? __ldg(sdf + cB.b1 + 4) : 0.0f;
    float ae0b = cB.wrap ? __ldg(gym + cB.b0 + 4) : 0.0f;
    float ae1b = cB.wrap ? __ldg(gym + cB.b1 + 4) : 0.0f;
    float be0b = cB.wrap ? __ldg(gxm + cB.b0 + 4) : 0.0f;
    float be1b = cB.wrap ? __ldg(gxm + cB.b1 + 4) : 0.0f;

    float costA, judgeA, costB, judgeB;
    finish(cA, S0a, S1a, A0a, A1a, B0a, B1a,
           se0a, se1a, ae0a, ae1a, be0a, be1a, costA, judgeA);
    finish(cB, S0b, S1b, A0b, A1b, B0b, B1b,
           se0b, se1b, ae0b, ae1b, be0b, be1b, costB, judgeB);

    out_res[i0]   = costA;
    out_judge[i0] = judgeA;
    if (has2) {
        out_res[i1]   = costB;
        out_judge[i1] = judgeB;
    }
}

extern "C" void kernel_launch(void* const* d_in, const int* in_sizes, int n_in,
                              void* d_out, int out_size)
{
    const float4* state = (const float4*)d_in[0];
    const float*  sdf   = (const float*)d_in[1];
    const float*  gym   = (const float*)d_in[2];
    const float*  gxm   = (const float*)d_in[3];
    float* out = (float*)d_out;

    int n = in_sizes[0] / 4;
    float* out_res   = out;
    float* out_judge = out + n;

    int threads = 256;
    int ptsPerBlock = threads * 2;
    int blocks = (n + ptsPerBlock - 1) / ptsPerBlock;
    imgmove_cost_kernel<<<blocks, threads>>>(state, sdf, gym, gxm,
                                             out_res, out_judge, n);
}